// round 2
// baseline (speedup 1.0000x reference)
#include <cuda_runtime.h>
#include <cstdint>
#include <cstddef>

// Problem dims (fixed): B=4, T=2048 -> BT=8192 tokens, D=1024, E=8, I=1024
#define BT_ 8192
#define D_  1024
#define E_  8
#define I_  1024

#define GOLDEN_CENTER 0.36787944117144233f
#define GOLDEN_LOWER  0.21231792754821915f
#define GOLDEN_UPPER  0.5f

// Scratch (device-global statics; no allocation at runtime)
__device__ float g_h[(size_t)E_ * BT_ * I_];   // 256 MB: h[e][t][i] fp32
__device__ float g_w[BT_ * E_];                // routing weights [t][e]

// ---------------------------------------------------------------------------
// helpers
// ---------------------------------------------------------------------------
__device__ __forceinline__ uint32_t f2tf(float x) {
    uint32_t r;
    asm("cvt.rna.tf32.f32 %0, %1;" : "=r"(r) : "f"(x));
    return r;
}
__device__ __forceinline__ void split2(float v, uint32_t& hi, uint32_t& lo) {
    uint32_t h = f2tf(v);
    hi = h;
    lo = f2tf(v - __uint_as_float(h));
}
__device__ __forceinline__ void mma8(float c[4], const uint32_t a[4], const uint32_t b[2]) {
    asm volatile(
        "mma.sync.aligned.m16n8k8.row.col.f32.tf32.tf32.f32 "
        "{%0,%1,%2,%3},{%4,%5,%6,%7},{%8,%9},{%0,%1,%2,%3};\n"
        : "+f"(c[0]), "+f"(c[1]), "+f"(c[2]), "+f"(c[3])
        : "r"(a[0]), "r"(a[1]), "r"(a[2]), "r"(a[3]), "r"(b[0]), "r"(b[1]));
}
__device__ __forceinline__ void cp16(uint32_t dst, const void* src) {
    asm volatile("cp.async.cg.shared.global [%0], [%1], 16;\n" :: "r"(dst), "l"(src) : "memory");
}
__device__ __forceinline__ void cpcommit() { asm volatile("cp.async.commit_group;\n" ::: "memory"); }
__device__ __forceinline__ void cpwait0()  { asm volatile("cp.async.wait_group 0;\n" ::: "memory"); }

__device__ __forceinline__ float siluf(float v) { return v / (1.0f + expf(-v)); }

// smem strides (words). Chosen conflict-free for the tf32 fragment patterns:
//   A frag read addr = g*20 + tg       -> banks (20g+tg)%32 all distinct
//   B frag read addr = tg*72 + g       -> banks (8tg+g)%32  all distinct
#define ASTR 20   // 16 K-words + 4 pad
#define BSTR 72   // 64 N-words + 8 pad
#define KT   16   // K per stage (2 mma k-steps)

// ---------------------------------------------------------------------------
// Routing weights kernel: one warp per token
// ---------------------------------------------------------------------------
__global__ __launch_bounds__(256) void routing_kernel(
    const float* __restrict__ x, const float* __restrict__ Wr,
    const float* __restrict__ temp)
{
    int warp = threadIdx.x >> 5;
    int lane = threadIdx.x & 31;
    int t = blockIdx.x * 8 + warp;   // 1024 blocks * 8 warps = 8192 tokens

    const float* xr = x + (size_t)t * D_;
    double acc[E_];
#pragma unroll
    for (int e = 0; e < E_; e++) acc[e] = 0.0;

    for (int d = lane; d < D_; d += 32) {
        float xv = xr[d];
#pragma unroll
        for (int e = 0; e < E_; e++)
            acc[e] += (double)xv * (double)Wr[d * E_ + e];
    }
#pragma unroll
    for (int off = 16; off > 0; off >>= 1) {
#pragma unroll
        for (int e = 0; e < E_; e++)
            acc[e] += __shfl_down_sync(0xffffffffu, acc[e], off);
    }

    if (lane == 0) {
        float T = temp[0];
        float dist[E_], wv[E_];
        float wsum = 0.0f;
#pragma unroll
        for (int e = 0; e < E_; e++) {
            float z = (float)acc[e] / T;
            float inh = 1.0f / (1.0f + expf(-z));
            dist[e] = fabsf(inh - GOLDEN_CENTER);
            bool zone = (inh >= GOLDEN_LOWER) && (inh <= GOLDEN_UPPER);
            wv[e] = zone ? expf(-dist[e] / 0.1f) : 0.0f;
            wsum += wv[e];
        }
        if (wsum < 1e-8f) {
            float fb[E_];
#pragma unroll
            for (int e = 0; e < E_; e++) fb[e] = expf(-dist[e] / 0.3f);
            int i1 = 0;
#pragma unroll
            for (int e = 1; e < E_; e++) if (fb[e] > fb[i1]) i1 = e;   // first max
            int i2 = (i1 == 0) ? 1 : 0;
#pragma unroll
            for (int e = 0; e < E_; e++)
                if (e != i1 && fb[e] > fb[i2]) i2 = e;                 // second max
            float s = fmaxf(fb[i1] + fb[i2], 1e-8f);
#pragma unroll
            for (int e = 0; e < E_; e++)
                wv[e] = (e == i1 || e == i2) ? fb[e] / s : 0.0f;
        }
        float s2 = 0.0f;
#pragma unroll
        for (int e = 0; e < E_; e++) s2 += wv[e];
        float inv = 1.0f / fmaxf(s2, 1e-8f);
#pragma unroll
        for (int e = 0; e < E_; e++) g_w[t * E_ + e] = wv[e] * inv;
    }
}

// ---------------------------------------------------------------------------
// Pass A: h[e] = silu(X @ Wg_e) * (X @ Wu_e)
// block tile: 128 tokens x 64 I-cols, dual GEMM (gate+up), K=1024
// grid (I/64, BT/128, E)
// ---------------------------------------------------------------------------
__global__ __launch_bounds__(256, 2) void passA_kernel(
    const float* __restrict__ x,
    const float* __restrict__ Wg, const float* __restrict__ Wu)
{
    __shared__ float As[2][128 * ASTR];
    __shared__ float Bg[2][KT * BSTR];
    __shared__ float Bu[2][KT * BSTR];

    const int e  = blockIdx.z;
    const int m0 = blockIdx.y * 128;
    const int n0 = blockIdx.x * 64;
    const float* Ap  = x + (size_t)m0 * D_;
    const float* Bgp = Wg + (size_t)e * D_ * I_ + n0;
    const float* Bup = Wu + (size_t)e * D_ * I_ + n0;

    const int tid  = threadIdx.x;
    const int lane = tid & 31, warp = tid >> 5;
    const int wm = warp & 3, wn = warp >> 2;
    const int g  = lane >> 2, tg = lane & 3;

    const uint32_t as_b = (uint32_t)__cvta_generic_to_shared(&As[0][0]);
    const uint32_t bg_b = (uint32_t)__cvta_generic_to_shared(&Bg[0][0]);
    const uint32_t bu_b = (uint32_t)__cvta_generic_to_shared(&Bu[0][0]);

    float cg[2][4][4], cu[2][4][4];
#pragma unroll
    for (int mt = 0; mt < 2; mt++)
#pragma unroll
        for (int nt = 0; nt < 4; nt++)
#pragma unroll
            for (int i = 0; i < 4; i++) { cg[mt][nt][i] = 0.0f; cu[mt][nt][i] = 0.0f; }

    // cp.async load indices
    const int a_r0 = tid >> 2, a_c = (tid & 3) << 2;       // + second row a_r0+64
    const int b_kr = tid >> 4, b_c = (tid & 15) << 2;

    const int S = D_ / KT;   // 64 stages

    // prologue: stage 0
    {
        cp16(as_b + (size_t)0 + (a_r0 * ASTR + a_c) * 4u,          Ap + (size_t)a_r0 * D_ + a_c);
        cp16(as_b + ((a_r0 + 64) * ASTR + a_c) * 4u,               Ap + (size_t)(a_r0 + 64) * D_ + a_c);
        cp16(bg_b + (b_kr * BSTR + b_c) * 4u,                      Bgp + (size_t)b_kr * I_ + b_c);
        cp16(bu_b + (b_kr * BSTR + b_c) * 4u,                      Bup + (size_t)b_kr * I_ + b_c);
        cpcommit();
    }

#pragma unroll 1
    for (int s = 0; s < S; s++) {
        cpwait0();
        __syncthreads();
        if (s + 1 < S) {
            int k0 = (s + 1) * KT;
            int bo = ((s + 1) & 1);
            cp16(as_b + (bo * 128 * ASTR + a_r0 * ASTR + a_c) * 4u,        Ap + (size_t)a_r0 * D_ + k0 + a_c);
            cp16(as_b + (bo * 128 * ASTR + (a_r0 + 64) * ASTR + a_c) * 4u, Ap + (size_t)(a_r0 + 64) * D_ + k0 + a_c);
            cp16(bg_b + (bo * KT * BSTR + b_kr * BSTR + b_c) * 4u,         Bgp + (size_t)(k0 + b_kr) * I_ + b_c);
            cp16(bu_b + (bo * KT * BSTR + b_kr * BSTR + b_c) * 4u,         Bup + (size_t)(k0 + b_kr) * I_ + b_c);
            cpcommit();
        }
        const float* Ab  = As[s & 1];
        const float* Bgf = Bg[s & 1];
        const float* Buf = Bu[s & 1];

#pragma unroll
        for (int ks = 0; ks < 2; ks++) {
            const int kk = ks * 8;
            uint32_t ah[2][4], al[2][4];
#pragma unroll
            for (int mt = 0; mt < 2; mt++) {
                int rb = wm * 32 + mt * 16;
                split2(Ab[(rb + g) * ASTR + kk + tg],        ah[mt][0], al[mt][0]);
                split2(Ab[(rb + g + 8) * ASTR + kk + tg],    ah[mt][1], al[mt][1]);
                split2(Ab[(rb + g) * ASTR + kk + tg + 4],    ah[mt][2], al[mt][2]);
                split2(Ab[(rb + g + 8) * ASTR + kk + tg + 4],ah[mt][3], al[mt][3]);
            }
#pragma unroll
            for (int nt = 0; nt < 4; nt++) {
                int col = wn * 32 + nt * 8 + g;
                uint32_t bh[2], bl[2], uh[2], ul[2];
                split2(Bgf[(kk + tg) * BSTR + col],     bh[0], bl[0]);
                split2(Bgf[(kk + tg + 4) * BSTR + col], bh[1], bl[1]);
                split2(Buf[(kk + tg) * BSTR + col],     uh[0], ul[0]);
                split2(Buf[(kk + tg + 4) * BSTR + col], uh[1], ul[1]);
#pragma unroll
                for (int mt = 0; mt < 2; mt++) {
                    mma8(cg[mt][nt], ah[mt], bh);
                    mma8(cg[mt][nt], al[mt], bh);
                    mma8(cg[mt][nt], ah[mt], bl);
                    mma8(cu[mt][nt], ah[mt], uh);
                    mma8(cu[mt][nt], al[mt], uh);
                    mma8(cu[mt][nt], ah[mt], ul);
                }
            }
        }
    }

    // epilogue: h = silu(gate) * up, write fp32
    float* hp = g_h + (size_t)e * BT_ * I_;
#pragma unroll
    for (int mt = 0; mt < 2; mt++) {
        int r0 = m0 + wm * 32 + mt * 16 + g;
#pragma unroll
        for (int nt = 0; nt < 4; nt++) {
            int c0 = n0 + wn * 32 + nt * 8 + tg * 2;
            float h0 = siluf(cg[mt][nt][0]) * cu[mt][nt][0];
            float h1 = siluf(cg[mt][nt][1]) * cu[mt][nt][1];
            float h2 = siluf(cg[mt][nt][2]) * cu[mt][nt][2];
            float h3 = siluf(cg[mt][nt][3]) * cu[mt][nt][3];
            *(float2*)(hp + (size_t)r0 * I_ + c0)       = make_float2(h0, h1);
            *(float2*)(hp + (size_t)(r0 + 8) * I_ + c0) = make_float2(h2, h3);
        }
    }
}

// ---------------------------------------------------------------------------
// Pass B: out = sum_e w[:,e] .* (h[e] @ Wd_e)
// block tile: 128 tokens x 64 D-cols, loops all 8 experts; grid (D/64, BT/128)
// ---------------------------------------------------------------------------
__global__ __launch_bounds__(256, 2) void passB_kernel(
    const float* __restrict__ Wd, float* __restrict__ out)
{
    __shared__ float As[2][128 * ASTR];
    __shared__ float Bs[2][KT * BSTR];
    __shared__ float ws[128][E_];

    const int m0 = blockIdx.y * 128;
    const int n0 = blockIdx.x * 64;

    const int tid  = threadIdx.x;
    const int lane = tid & 31, warp = tid >> 5;
    const int wm = warp & 3, wn = warp >> 2;
    const int g  = lane >> 2, tg = lane & 3;

    const uint32_t as_b = (uint32_t)__cvta_generic_to_shared(&As[0][0]);
    const uint32_t bs_b = (uint32_t)__cvta_generic_to_shared(&Bs[0][0]);

    // stage routing weights for this token tile
    for (int idx = tid; idx < 128 * E_; idx += 256)
        ws[idx >> 3][idx & 7] = g_w[(m0 + (idx >> 3)) * E_ + (idx & 7)];

    float acc[2][4][4];
#pragma unroll
    for (int mt = 0; mt < 2; mt++)
#pragma unroll
        for (int nt = 0; nt < 4; nt++)
#pragma unroll
            for (int i = 0; i < 4; i++) acc[mt][nt][i] = 0.0f;

    const int a_r0 = tid >> 2, a_c = (tid & 3) << 2;
    const int b_kr = tid >> 4, b_c = (tid & 15) << 2;
    const int S = I_ / KT;   // 64 stages per expert

#pragma unroll 1
    for (int e = 0; e < E_; e++) {
        const float* Ap = g_h + ((size_t)e * BT_ + m0) * I_;
        const float* Bp = Wd + (size_t)e * I_ * D_ + n0;

        float part[2][4][4];
#pragma unroll
        for (int mt = 0; mt < 2; mt++)
#pragma unroll
            for (int nt = 0; nt < 4; nt++)
#pragma unroll
                for (int i = 0; i < 4; i++) part[mt][nt][i] = 0.0f;

        // prologue stage 0
        __syncthreads();   // protect smem reuse across experts / ws staging
        cp16(as_b + (a_r0 * ASTR + a_c) * 4u,          Ap + (size_t)a_r0 * I_ + a_c);
        cp16(as_b + ((a_r0 + 64) * ASTR + a_c) * 4u,   Ap + (size_t)(a_r0 + 64) * I_ + a_c);
        cp16(bs_b + (b_kr * BSTR + b_c) * 4u,          Bp + (size_t)b_kr * D_ + b_c);
        cpcommit();

#pragma unroll 1
        for (int s = 0; s < S; s++) {
            cpwait0();
            __syncthreads();
            if (s + 1 < S) {
                int k0 = (s + 1) * KT;
                int bo = ((s + 1) & 1);
                cp16(as_b + (bo * 128 * ASTR + a_r0 * ASTR + a_c) * 4u,        Ap + (size_t)a_r0 * I_ + k0 + a_c);
                cp16(as_b + (bo * 128 * ASTR + (a_r0 + 64) * ASTR + a_c) * 4u, Ap + (size_t)(a_r0 + 64) * I_ + k0 + a_c);
                cp16(bs_b + (bo * KT * BSTR + b_kr * BSTR + b_c) * 4u,         Bp + (size_t)(k0 + b_kr) * D_ + b_c);
                cpcommit();
            }
            const float* Ab = As[s & 1];
            const float* Bf = Bs[s & 1];

#pragma unroll
            for (int ks = 0; ks < 2; ks++) {
                const int kk = ks * 8;
                uint32_t ah[2][4], al[2][4];
#pragma unroll
                for (int mt = 0; mt < 2; mt++) {
                    int rb = wm * 32 + mt * 16;
                    split2(Ab[(rb + g) * ASTR + kk + tg],         ah[mt][0], al[mt][0]);
                    split2(Ab[(rb + g + 8) * ASTR + kk + tg],     ah[mt][1], al[mt][1]);
                    split2(Ab[(rb + g) * ASTR + kk + tg + 4],     ah[mt][2], al[mt][2]);
                    split2(Ab[(rb + g + 8) * ASTR + kk + tg + 4], ah[mt][3], al[mt][3]);
                }
#pragma unroll
                for (int nt = 0; nt < 4; nt++) {
                    int col = wn * 32 + nt * 8 + g;
                    uint32_t bh[2], bl[2];
                    split2(Bf[(kk + tg) * BSTR + col],     bh[0], bl[0]);
                    split2(Bf[(kk + tg + 4) * BSTR + col], bh[1], bl[1]);
#pragma unroll
                    for (int mt = 0; mt < 2; mt++) {
                        mma8(part[mt][nt], ah[mt], bh);
                        mma8(part[mt][nt], al[mt], bh);
                        mma8(part[mt][nt], ah[mt], bl);
                    }
                }
            }
        }

        // apply per-token routing weight for this expert
#pragma unroll
        for (int mt = 0; mt < 2; mt++) {
            float w0 = ws[wm * 32 + mt * 16 + g][e];
            float w1 = ws[wm * 32 + mt * 16 + g + 8][e];
#pragma unroll
            for (int nt = 0; nt < 4; nt++) {
                acc[mt][nt][0] += w0 * part[mt][nt][0];
                acc[mt][nt][1] += w0 * part[mt][nt][1];
                acc[mt][nt][2] += w1 * part[mt][nt][2];
                acc[mt][nt][3] += w1 * part[mt][nt][3];
            }
        }
    }

    // write out
#pragma unroll
    for (int mt = 0; mt < 2; mt++) {
        int r0 = m0 + wm * 32 + mt * 16 + g;
#pragma unroll
        for (int nt = 0; nt < 4; nt++) {
            int c0 = n0 + wn * 32 + nt * 8 + tg * 2;
            *(float2*)(out + (size_t)r0 * D_ + c0)       = make_float2(acc[mt][nt][0], acc[mt][nt][1]);
            *(float2*)(out + (size_t)(r0 + 8) * D_ + c0) = make_float2(acc[mt][nt][2], acc[mt][nt][3]);
        }
    }
}

// ---------------------------------------------------------------------------
// launch
// ---------------------------------------------------------------------------
extern "C" void kernel_launch(void* const* d_in, const int* in_sizes, int n_in,
                              void* d_out, int out_size)
{
    const float* x    = (const float*)d_in[0];
    const float* Wg   = (const float*)d_in[1];
    const float* Wu   = (const float*)d_in[2];
    const float* Wd   = (const float*)d_in[3];
    const float* Wr   = (const float*)d_in[4];
    const float* temp = (const float*)d_in[5];
    float* out = (float*)d_out;

    routing_kernel<<<BT_ / 8, 256>>>(x, Wr, temp);

    dim3 gA(I_ / 64, BT_ / 128, E_);
    passA_kernel<<<gA, 256>>>(x, Wg, Wu);

    dim3 gB(D_ / 64, BT_ / 128);
    passB_kernel<<<gB, 256>>>(Wd, out);
}

// round 3
// speedup vs baseline: 1.8082x; 1.8082x over previous
#include <cuda_runtime.h>
#include <cuda_bf16.h>
#include <cstdint>
#include <cstddef>

// Problem dims: B=4, T=2048 -> BT=8192 tokens, D=1024, E=8, I=1024
#define BT_ 8192
#define D_  1024
#define E_  8
#define I_  1024

#define GOLDEN_CENTER 0.36787944117144233f
#define GOLDEN_LOWER  0.21231792754821915f
#define GOLDEN_UPPER  0.5f

// ---------------------------------------------------------------------------
// Device scratch (static; no runtime allocation)
// ---------------------------------------------------------------------------
__device__ __nv_bfloat16 g_xh[BT_ * D_], g_xl[BT_ * D_];                 // x hi/lo [t][d]
__device__ __nv_bfloat16 g_wgh[E_ * D_ * I_], g_wgl[E_ * D_ * I_];       // Wg^T hi/lo [e][i][d]
__device__ __nv_bfloat16 g_wuh[E_ * D_ * I_], g_wul[E_ * D_ * I_];       // Wu^T hi/lo [e][i][d]
__device__ __nv_bfloat16 g_wdh[E_ * D_ * I_], g_wdl[E_ * D_ * I_];       // Wd^T hi/lo [e][d][i]
__device__ __nv_bfloat16 g_hh[(size_t)E_ * BT_ * I_];                    // h hi [e][t][i]
__device__ __nv_bfloat16 g_hl[(size_t)E_ * BT_ * I_];                    // h lo
__device__ float g_w[BT_ * E_];                                          // routing weights

// ---------------------------------------------------------------------------
// helpers
// ---------------------------------------------------------------------------
__device__ __forceinline__ void mma16(float c[4], const uint32_t a[4], const uint32_t b[2]) {
    asm volatile(
        "mma.sync.aligned.m16n8k16.row.col.f32.bf16.bf16.f32 "
        "{%0,%1,%2,%3},{%4,%5,%6,%7},{%8,%9},{%0,%1,%2,%3};\n"
        : "+f"(c[0]), "+f"(c[1]), "+f"(c[2]), "+f"(c[3])
        : "r"(a[0]), "r"(a[1]), "r"(a[2]), "r"(a[3]), "r"(b[0]), "r"(b[1]));
}
__device__ __forceinline__ void ldsm4(uint32_t r[4], uint32_t addr) {
    asm volatile("ldmatrix.sync.aligned.m8n8.x4.shared.b16 {%0,%1,%2,%3}, [%4];"
        : "=r"(r[0]), "=r"(r[1]), "=r"(r[2]), "=r"(r[3]) : "r"(addr));
}
__device__ __forceinline__ void cp16(uint32_t dst, const void* src) {
    asm volatile("cp.async.cg.shared.global [%0], [%1], 16;\n" :: "r"(dst), "l"(src) : "memory");
}
__device__ __forceinline__ void cpcommit() { asm volatile("cp.async.commit_group;\n" ::: "memory"); }
__device__ __forceinline__ void cpwait0()  { asm volatile("cp.async.wait_group 0;\n" ::: "memory"); }
__device__ __forceinline__ float siluf(float v) { return v / (1.0f + expf(-v)); }

// smem row stride: 20 words (16 data + 4 pad). Rows are 80B = 16B-aligned, and
// chunk index 5r mod 8 is a permutation -> ldmatrix conflict-free.
#define RSTR 20
#define KT   32   // K per stage (2 mma k16 steps)

// ---------------------------------------------------------------------------
// Routing weights: one warp per token (UNCHANGED from passing version)
// ---------------------------------------------------------------------------
__global__ __launch_bounds__(256) void routing_kernel(
    const float* __restrict__ x, const float* __restrict__ Wr,
    const float* __restrict__ temp)
{
    int warp = threadIdx.x >> 5;
    int lane = threadIdx.x & 31;
    int t = blockIdx.x * 8 + warp;

    const float* xr = x + (size_t)t * D_;
    double acc[E_];
#pragma unroll
    for (int e = 0; e < E_; e++) acc[e] = 0.0;

    for (int d = lane; d < D_; d += 32) {
        float xv = xr[d];
#pragma unroll
        for (int e = 0; e < E_; e++)
            acc[e] += (double)xv * (double)Wr[d * E_ + e];
    }
#pragma unroll
    for (int off = 16; off > 0; off >>= 1) {
#pragma unroll
        for (int e = 0; e < E_; e++)
            acc[e] += __shfl_down_sync(0xffffffffu, acc[e], off);
    }

    if (lane == 0) {
        float T = temp[0];
        float dist[E_], wv[E_];
        float wsum = 0.0f;
#pragma unroll
        for (int e = 0; e < E_; e++) {
            float z = (float)acc[e] / T;
            float inh = 1.0f / (1.0f + expf(-z));
            dist[e] = fabsf(inh - GOLDEN_CENTER);
            bool zone = (inh >= GOLDEN_LOWER) && (inh <= GOLDEN_UPPER);
            wv[e] = zone ? expf(-dist[e] / 0.1f) : 0.0f;
            wsum += wv[e];
        }
        if (wsum < 1e-8f) {
            float fb[E_];
#pragma unroll
            for (int e = 0; e < E_; e++) fb[e] = expf(-dist[e] / 0.3f);
            int i1 = 0;
#pragma unroll
            for (int e = 1; e < E_; e++) if (fb[e] > fb[i1]) i1 = e;
            int i2 = (i1 == 0) ? 1 : 0;
#pragma unroll
            for (int e = 0; e < E_; e++)
                if (e != i1 && fb[e] > fb[i2]) i2 = e;
            float s = fmaxf(fb[i1] + fb[i2], 1e-8f);
#pragma unroll
            for (int e = 0; e < E_; e++)
                wv[e] = (e == i1 || e == i2) ? fb[e] / s : 0.0f;
        }
        float s2 = 0.0f;
#pragma unroll
        for (int e = 0; e < E_; e++) s2 += wv[e];
        float inv = 1.0f / fmaxf(s2, 1e-8f);
#pragma unroll
        for (int e = 0; e < E_; e++) g_w[t * E_ + e] = wv[e] * inv;
    }
}

// ---------------------------------------------------------------------------
// convert x -> hi/lo bf16
// ---------------------------------------------------------------------------
__global__ __launch_bounds__(256) void convx_kernel(const float* __restrict__ x)
{
    int i = (blockIdx.x * 256 + threadIdx.x) * 4;
    float4 v = *(const float4*)(x + i);
    float f[4] = {v.x, v.y, v.z, v.w};
    __nv_bfloat16 h[4], l[4];
#pragma unroll
    for (int j = 0; j < 4; j++) {
        h[j] = __float2bfloat16_rn(f[j]);
        l[j] = __float2bfloat16_rn(f[j] - __bfloat162float(h[j]));
    }
    __nv_bfloat162 p;
    p.x = h[0]; p.y = h[1]; *(__nv_bfloat162*)(g_xh + i) = p;
    p.x = h[2]; p.y = h[3]; *(__nv_bfloat162*)(g_xh + i + 2) = p;
    p.x = l[0]; p.y = l[1]; *(__nv_bfloat162*)(g_xl + i) = p;
    p.x = l[2]; p.y = l[3]; *(__nv_bfloat162*)(g_xl + i + 2) = p;
}

// ---------------------------------------------------------------------------
// transpose + split: out[e][c][r] = split(in[e][r][c]),  1024x1024 per expert
// ---------------------------------------------------------------------------
__global__ __launch_bounds__(256) void convT_kernel(
    const float* __restrict__ in, __nv_bfloat16* __restrict__ oh,
    __nv_bfloat16* __restrict__ ol)
{
    __shared__ float t[32][33];
    int e = blockIdx.z;
    const float* ip = in + (size_t)e * 1024 * 1024;
    __nv_bfloat16* ohp = oh + (size_t)e * 1024 * 1024;
    __nv_bfloat16* olp = ol + (size_t)e * 1024 * 1024;
    int r0 = blockIdx.y * 32, c0 = blockIdx.x * 32;
    int tx = threadIdx.x, ty = threadIdx.y;

#pragma unroll
    for (int j = ty; j < 32; j += 8)
        t[j][tx] = ip[(size_t)(r0 + j) * 1024 + c0 + tx];
    __syncthreads();
#pragma unroll
    for (int j = ty; j < 32; j += 8) {
        float v = t[tx][j];
        __nv_bfloat16 h = __float2bfloat16_rn(v);
        ohp[(size_t)(c0 + j) * 1024 + r0 + tx] = h;
        olp[(size_t)(c0 + j) * 1024 + r0 + tx] =
            __float2bfloat16_rn(v - __bfloat162float(h));
    }
}

// ---------------------------------------------------------------------------
// Pass A: h[e] = silu(X @ Wg_e) * (X @ Wu_e)  (bf16 hi/lo 3-term split)
// block 128m x 64n, 8 warps (4m x 2n), warp 32x32; grid (16, 64, 8)
// ---------------------------------------------------------------------------
__global__ __launch_bounds__(256) void passA_kernel()
{
    extern __shared__ char smem[];
    const uint32_t sb = (uint32_t)__cvta_generic_to_shared(smem);
    // region byte offsets (2 stages each): A 2*10240, B 2*5120 per component
    const uint32_t oAh = 0, oAl = 20480, oGh = 40960, oGl = 51200, oUh = 61440, oUl = 71680;

    const int e  = blockIdx.z;
    const int m0 = blockIdx.y * 128;
    const int n0 = blockIdx.x * 64;

    const __nv_bfloat16* Axh = g_xh + (size_t)m0 * D_;
    const __nv_bfloat16* Axl = g_xl + (size_t)m0 * D_;
    const __nv_bfloat16* Gh  = g_wgh + ((size_t)e * I_ + n0) * D_;
    const __nv_bfloat16* Gl  = g_wgl + ((size_t)e * I_ + n0) * D_;
    const __nv_bfloat16* Uh  = g_wuh + ((size_t)e * I_ + n0) * D_;
    const __nv_bfloat16* Ul  = g_wul + ((size_t)e * I_ + n0) * D_;

    const int tid = threadIdx.x, lane = tid & 31, warp = tid >> 5;
    const int wm = warp & 3, wn = warp >> 2;

    // cp.async mapping: lr in [0,64), chunk lc in [0,4) (16B chunks of a 64B row)
    const int lr = tid >> 2, lc = tid & 3;
    const uint32_t adst1 = (uint32_t)((lr)      * RSTR + lc * 4) * 4;
    const uint32_t adst2 = (uint32_t)((lr + 64) * RSTR + lc * 4) * 4;
    const uint32_t bdst  = adst1;
    const size_t asrc1 = (size_t)lr * D_ + lc * 8;
    const size_t asrc2 = (size_t)(lr + 64) * D_ + lc * 8;
    const size_t bsrc  = (size_t)lr * D_ + lc * 8;

    // ldmatrix per-lane offsets (bytes)
    const uint32_t aoffL = (uint32_t)((((lane & 7) + ((lane >> 3) & 1) * 8) * RSTR + (lane >> 4) * 4)) * 4;
    const uint32_t boffL = (uint32_t)((((lane & 7) + (lane >> 4) * 8) * RSTR + ((lane >> 3) & 1) * 4)) * 4;

    float cg[2][4][4], cu[2][4][4];
#pragma unroll
    for (int mt = 0; mt < 2; mt++)
#pragma unroll
        for (int nt = 0; nt < 4; nt++)
#pragma unroll
            for (int i = 0; i < 4; i++) { cg[mt][nt][i] = 0.0f; cu[mt][nt][i] = 0.0f; }

#define ISSUE_A(buf, k0) do {                                            \
        uint32_t ao = (uint32_t)(buf) * 10240u, bo = (uint32_t)(buf) * 5120u; \
        cp16(sb + oAh + ao + adst1, Axh + asrc1 + (k0));                 \
        cp16(sb + oAh + ao + adst2, Axh + asrc2 + (k0));                 \
        cp16(sb + oAl + ao + adst1, Axl + asrc1 + (k0));                 \
        cp16(sb + oAl + ao + adst2, Axl + asrc2 + (k0));                 \
        cp16(sb + oGh + bo + bdst,  Gh + bsrc + (k0));                   \
        cp16(sb + oGl + bo + bdst,  Gl + bsrc + (k0));                   \
        cp16(sb + oUh + bo + bdst,  Uh + bsrc + (k0));                   \
        cp16(sb + oUl + bo + bdst,  Ul + bsrc + (k0));                   \
        cpcommit();                                                      \
    } while (0)

    ISSUE_A(0, 0);

#pragma unroll 1
    for (int s = 0; s < D_ / KT; s++) {
        cpwait0();
        __syncthreads();
        if (s + 1 < D_ / KT) ISSUE_A((s + 1) & 1, (s + 1) * KT);
        const uint32_t ab = (uint32_t)(s & 1) * 10240u;
        const uint32_t bb = (uint32_t)(s & 1) * 5120u;

#pragma unroll
        for (int ks = 0; ks < 2; ks++) {
            const uint32_t kkb = (uint32_t)ks * 32u;   // 8 words * 4B
            uint32_t ah[2][4], al[2][4];
#pragma unroll
            for (int mt = 0; mt < 2; mt++) {
                uint32_t ro = (uint32_t)((wm * 32 + mt * 16) * RSTR * 4);
                ldsm4(ah[mt], sb + oAh + ab + ro + aoffL + kkb);
                ldsm4(al[mt], sb + oAl + ab + ro + aoffL + kkb);
            }
            uint32_t gh[2][4], gl[2][4], uh[2][4], ul[2][4];
#pragma unroll
            for (int p = 0; p < 2; p++) {
                uint32_t ro = (uint32_t)((wn * 32 + p * 16) * RSTR * 4);
                ldsm4(gh[p], sb + oGh + bb + ro + boffL + kkb);
                ldsm4(gl[p], sb + oGl + bb + ro + boffL + kkb);
                ldsm4(uh[p], sb + oUh + bb + ro + boffL + kkb);
                ldsm4(ul[p], sb + oUl + bb + ro + boffL + kkb);
            }
#pragma unroll
            for (int mt = 0; mt < 2; mt++)
#pragma unroll
                for (int p = 0; p < 2; p++)
#pragma unroll
                    for (int q = 0; q < 2; q++) {
                        const int nt = 2 * p + q;
                        mma16(cg[mt][nt], ah[mt], &gh[p][2 * q]);
                        mma16(cg[mt][nt], al[mt], &gh[p][2 * q]);
                        mma16(cg[mt][nt], ah[mt], &gl[p][2 * q]);
                        mma16(cu[mt][nt], ah[mt], &uh[p][2 * q]);
                        mma16(cu[mt][nt], al[mt], &uh[p][2 * q]);
                        mma16(cu[mt][nt], ah[mt], &ul[p][2 * q]);
                    }
        }
    }
#undef ISSUE_A

    // epilogue: h = silu(gate)*up -> split hi/lo bf16
    const int g = lane >> 2, tg = lane & 3;
    __nv_bfloat16* Hh = g_hh + (size_t)e * BT_ * I_;
    __nv_bfloat16* Hl = g_hl + (size_t)e * BT_ * I_;
#pragma unroll
    for (int mt = 0; mt < 2; mt++) {
        int r0 = m0 + wm * 32 + mt * 16 + g;
#pragma unroll
        for (int nt = 0; nt < 4; nt++) {
            int c0 = n0 + wn * 32 + nt * 8 + tg * 2;
            float h0 = siluf(cg[mt][nt][0]) * cu[mt][nt][0];
            float h1 = siluf(cg[mt][nt][1]) * cu[mt][nt][1];
            float h2 = siluf(cg[mt][nt][2]) * cu[mt][nt][2];
            float h3 = siluf(cg[mt][nt][3]) * cu[mt][nt][3];
            __nv_bfloat162 ph, pl;
            ph.x = __float2bfloat16_rn(h0); ph.y = __float2bfloat16_rn(h1);
            pl.x = __float2bfloat16_rn(h0 - __bfloat162float(ph.x));
            pl.y = __float2bfloat16_rn(h1 - __bfloat162float(ph.y));
            *(__nv_bfloat162*)(Hh + (size_t)r0 * I_ + c0) = ph;
            *(__nv_bfloat162*)(Hl + (size_t)r0 * I_ + c0) = pl;
            ph.x = __float2bfloat16_rn(h2); ph.y = __float2bfloat16_rn(h3);
            pl.x = __float2bfloat16_rn(h2 - __bfloat162float(ph.x));
            pl.y = __float2bfloat16_rn(h3 - __bfloat162float(ph.y));
            *(__nv_bfloat162*)(Hh + (size_t)(r0 + 8) * I_ + c0) = ph;
            *(__nv_bfloat162*)(Hl + (size_t)(r0 + 8) * I_ + c0) = pl;
        }
    }
}

// ---------------------------------------------------------------------------
// Pass B: out = sum_e w[:,e] .* (h[e] @ Wd_e)
// block 128m x 64n, loops experts; grid (16, 64)
// ---------------------------------------------------------------------------
__global__ __launch_bounds__(256) void passB_kernel(float* __restrict__ out)
{
    extern __shared__ char smem[];
    const uint32_t sb = (uint32_t)__cvta_generic_to_shared(smem);
    const uint32_t oAh = 0, oAl = 20480, oBh = 40960, oBl = 51200;
    __shared__ float ws[128][E_];

    const int m0 = blockIdx.y * 128;
    const int n0 = blockIdx.x * 64;

    const int tid = threadIdx.x, lane = tid & 31, warp = tid >> 5;
    const int wm = warp & 3, wn = warp >> 2;

    for (int idx = tid; idx < 128 * E_; idx += 256)
        ws[idx >> 3][idx & 7] = g_w[(m0 + (idx >> 3)) * E_ + (idx & 7)];

    const int lr = tid >> 2, lc = tid & 3;
    const uint32_t adst1 = (uint32_t)((lr)      * RSTR + lc * 4) * 4;
    const uint32_t adst2 = (uint32_t)((lr + 64) * RSTR + lc * 4) * 4;
    const uint32_t bdst  = adst1;
    const size_t asrc1 = (size_t)lr * I_ + lc * 8;
    const size_t asrc2 = (size_t)(lr + 64) * I_ + lc * 8;
    const size_t bsrc  = (size_t)lr * I_ + lc * 8;

    const uint32_t aoffL = (uint32_t)((((lane & 7) + ((lane >> 3) & 1) * 8) * RSTR + (lane >> 4) * 4)) * 4;
    const uint32_t boffL = (uint32_t)((((lane & 7) + (lane >> 4) * 8) * RSTR + ((lane >> 3) & 1) * 4)) * 4;

    const int g = lane >> 2, tg = lane & 3;

    float acc[2][4][4];
#pragma unroll
    for (int mt = 0; mt < 2; mt++)
#pragma unroll
        for (int nt = 0; nt < 4; nt++)
#pragma unroll
            for (int i = 0; i < 4; i++) acc[mt][nt][i] = 0.0f;

#pragma unroll 1
    for (int e = 0; e < E_; e++) {
        const __nv_bfloat16* Ahp = g_hh + ((size_t)e * BT_ + m0) * I_;
        const __nv_bfloat16* Alp = g_hl + ((size_t)e * BT_ + m0) * I_;
        const __nv_bfloat16* Bhp = g_wdh + ((size_t)e * D_ + n0) * I_;
        const __nv_bfloat16* Blp = g_wdl + ((size_t)e * D_ + n0) * I_;

        float part[2][4][4];
#pragma unroll
        for (int mt = 0; mt < 2; mt++)
#pragma unroll
            for (int nt = 0; nt < 4; nt++)
#pragma unroll
                for (int i = 0; i < 4; i++) part[mt][nt][i] = 0.0f;

        __syncthreads();   // previous expert's compute done; ws staged (e=0)

#define ISSUE_B(buf, k0) do {                                            \
        uint32_t ao = (uint32_t)(buf) * 10240u, bo = (uint32_t)(buf) * 5120u; \
        cp16(sb + oAh + ao + adst1, Ahp + asrc1 + (k0));                 \
        cp16(sb + oAh + ao + adst2, Ahp + asrc2 + (k0));                 \
        cp16(sb + oAl + ao + adst1, Alp + asrc1 + (k0));                 \
        cp16(sb + oAl + ao + adst2, Alp + asrc2 + (k0));                 \
        cp16(sb + oBh + bo + bdst,  Bhp + bsrc + (k0));                  \
        cp16(sb + oBl + bo + bdst,  Blp + bsrc + (k0));                  \
        cpcommit();                                                      \
    } while (0)

        ISSUE_B(0, 0);

#pragma unroll 1
        for (int s = 0; s < I_ / KT; s++) {
            cpwait0();
            __syncthreads();
            if (s + 1 < I_ / KT) ISSUE_B((s + 1) & 1, (s + 1) * KT);
            const uint32_t ab = (uint32_t)(s & 1) * 10240u;
            const uint32_t bb = (uint32_t)(s & 1) * 5120u;

#pragma unroll
            for (int ks = 0; ks < 2; ks++) {
                const uint32_t kkb = (uint32_t)ks * 32u;
                uint32_t ah[2][4], al[2][4];
#pragma unroll
                for (int mt = 0; mt < 2; mt++) {
                    uint32_t ro = (uint32_t)((wm * 32 + mt * 16) * RSTR * 4);
                    ldsm4(ah[mt], sb + oAh + ab + ro + aoffL + kkb);
                    ldsm4(al[mt], sb + oAl + ab + ro + aoffL + kkb);
                }
                uint32_t bh[2][4], bl[2][4];
#pragma unroll
                for (int p = 0; p < 2; p++) {
                    uint32_t ro = (uint32_t)((wn * 32 + p * 16) * RSTR * 4);
                    ldsm4(bh[p], sb + oBh + bb + ro + boffL + kkb);
                    ldsm4(bl[p], sb + oBl + bb + ro + boffL + kkb);
                }
#pragma unroll
                for (int mt = 0; mt < 2; mt++)
#pragma unroll
                    for (int p = 0; p < 2; p++)
#pragma unroll
                        for (int q = 0; q < 2; q++) {
                            const int nt = 2 * p + q;
                            mma16(part[mt][nt], ah[mt], &bh[p][2 * q]);
                            mma16(part[mt][nt], al[mt], &bh[p][2 * q]);
                            mma16(part[mt][nt], ah[mt], &bl[p][2 * q]);
                        }
            }
        }
#undef ISSUE_B

        // apply routing weight
#pragma unroll
        for (int mt = 0; mt < 2; mt++) {
            float w0 = ws[wm * 32 + mt * 16 + g][e];
            float w1 = ws[wm * 32 + mt * 16 + g + 8][e];
#pragma unroll
            for (int nt = 0; nt < 4; nt++) {
                acc[mt][nt][0] += w0 * part[mt][nt][0];
                acc[mt][nt][1] += w0 * part[mt][nt][1];
                acc[mt][nt][2] += w1 * part[mt][nt][2];
                acc[mt][nt][3] += w1 * part[mt][nt][3];
            }
        }
    }

#pragma unroll
    for (int mt = 0; mt < 2; mt++) {
        int r0 = m0 + wm * 32 + mt * 16 + g;
#pragma unroll
        for (int nt = 0; nt < 4; nt++) {
            int c0 = n0 + wn * 32 + nt * 8 + tg * 2;
            *(float2*)(out + (size_t)r0 * D_ + c0)       = make_float2(acc[mt][nt][0], acc[mt][nt][1]);
            *(float2*)(out + (size_t)(r0 + 8) * D_ + c0) = make_float2(acc[mt][nt][2], acc[mt][nt][3]);
        }
    }
}

// ---------------------------------------------------------------------------
// launch
// ---------------------------------------------------------------------------
extern "C" void kernel_launch(void* const* d_in, const int* in_sizes, int n_in,
                              void* d_out, int out_size)
{
    const float* x    = (const float*)d_in[0];
    const float* Wg   = (const float*)d_in[1];
    const float* Wu   = (const float*)d_in[2];
    const float* Wd   = (const float*)d_in[3];
    const float* Wr   = (const float*)d_in[4];
    const float* temp = (const float*)d_in[5];
    float* out = (float*)d_out;

    cudaFuncSetAttribute(passA_kernel, cudaFuncAttributeMaxDynamicSharedMemorySize, 81920);
    cudaFuncSetAttribute(passB_kernel, cudaFuncAttributeMaxDynamicSharedMemorySize, 61440);

    routing_kernel<<<BT_ / 8, 256>>>(x, Wr, temp);
    convx_kernel<<<BT_ * D_ / 1024, 256>>>(x);

    __nv_bfloat16 *wgh, *wgl, *wuh, *wul, *wdh, *wdl;
    cudaGetSymbolAddress((void**)&wgh, g_wgh);
    cudaGetSymbolAddress((void**)&wgl, g_wgl);
    cudaGetSymbolAddress((void**)&wuh, g_wuh);
    cudaGetSymbolAddress((void**)&wul, g_wul);
    cudaGetSymbolAddress((void**)&wdh, g_wdh);
    cudaGetSymbolAddress((void**)&wdl, g_wdl);

    dim3 gt(32, 32, E_), bt(32, 8);
    convT_kernel<<<gt, bt>>>(Wg, wgh, wgl);
    convT_kernel<<<gt, bt>>>(Wu, wuh, wul);
    convT_kernel<<<gt, bt>>>(Wd, wdh, wdl);

    dim3 gA(I_ / 64, BT_ / 128, E_);
    passA_kernel<<<gA, 256, 81920>>>();

    dim3 gB(D_ / 64, BT_ / 128);
    passB_kernel<<<gB, 256, 61440>>>(out);
}